// round 4
// baseline (speedup 1.0000x reference)
#include <cuda_runtime.h>
#include <cuda_bf16.h>
#include <cstdint>

// ---------------- problem constants ----------------
#define NTOK 1024
#define DIN  1024
// regions: [0,20000) head, [20000,40000), [40000,200000), [200000,267735)

// ---------------- GEMM tile config ----------------
#define TM 128
#define TN 128
#define KC 64
#define NKC 16              // DIN / KC
#define GT 256              // threads per CTA

// smem byte offsets (dynamic). Buffers 1024-aligned for SW128 swizzle atoms.
#define SA(buf) ((buf) * 16384)              // A: 2 x (128 rows x 128B)
#define SB(buf) (32768 + (buf) * 16384)      // B: 2 x (128 rows x 128B)
#define SBIAS 65536                          // 128 f32
#define SLIST 66048                          // 128 int
#define SROW  66560                          // 128 f32
#define SMEM_TOTAL 67072

#define SW(o) ((o) ^ (((o) >> 3) & 0x70))    // SW128 swizzle on byte offsets

// ---------------- device scratch (static; no allocation) ----------------
__device__ float g_S[4][NTOK];          // per-region per-token sum of exp
__device__ int   g_list[4][NTOK];       // compacted token lists
__device__ int   g_count[4];
__device__ float g_tlogit[NTOK];        // exact f32 target logit (incl bias)
__device__ float g_clogit[NTOK][3];     // exact f32 cluster logits (incl bias)
__device__ int   g_cid[NTOK];

// ---------------- small helpers ----------------
__device__ __forceinline__ uint32_t smem_u32(const void* p) {
    uint32_t a;
    asm("{ .reg .u64 t; cvta.to.shared.u64 t, %1; cvt.u32.u64 %0, t; }" : "=r"(a) : "l"(p));
    return a;
}
__device__ __forceinline__ uint32_t pack_bf16(float a, float b) {
    __nv_bfloat162 h = __floats2bfloat162_rn(a, b);
    return *reinterpret_cast<uint32_t*>(&h);
}
__device__ __forceinline__ void lds_frag4(uint32_t r[4], uint32_t addr) {
    asm volatile("ldmatrix.sync.aligned.m8n8.x4.shared.b16 {%0,%1,%2,%3}, [%4];"
        : "=r"(r[0]), "=r"(r[1]), "=r"(r[2]), "=r"(r[3]) : "r"(addr));
}
__device__ __forceinline__ void mma16816(float d[4], const uint32_t a[4],
                                         uint32_t b0, uint32_t b1) {
    asm volatile("mma.sync.aligned.m16n8k16.row.col.f32.bf16.bf16.f32 "
        "{%0,%1,%2,%3}, {%4,%5,%6,%7}, {%8,%9}, {%0,%1,%2,%3};"
        : "+f"(d[0]), "+f"(d[1]), "+f"(d[2]), "+f"(d[3])
        : "r"(a[0]), "r"(a[1]), "r"(a[2]), "r"(a[3]), "r"(b0), "r"(b1));
}

// ---------------- kernel 0: reset scratch ----------------
__global__ void zero_kernel() {
    int t = threadIdx.x;
    for (int i = t; i < 4 * NTOK; i += blockDim.x) (&g_S[0][0])[i] = 0.0f;
    for (int i = t; i < NTOK; i += blockDim.x) g_list[0][i] = i;
    if (t == 0) g_count[0] = NTOK;
    if (t >= 1 && t < 4) g_count[t] = 0;
}

// ---------------- kernel 1: per-token prep (exact f32 dots + compaction) ----------------
__global__ void prep_kernel(const float* __restrict__ hidden,
                            const int* __restrict__ target,   // int32 (JAX x64 disabled)
                            const float* __restrict__ weight,
                            const float* __restrict__ bias,
                            const float* __restrict__ cw,
                            const float* __restrict__ cb) {
    int gw = (int)((blockIdx.x * blockDim.x + threadIdx.x) >> 5);
    int lane = threadIdx.x & 31;
    if (gw >= NTOK) return;
    const int t = target[gw];
    const float4* h4  = reinterpret_cast<const float4*>(hidden + (size_t)gw * DIN);
    const float4* w4  = reinterpret_cast<const float4*>(weight + (size_t)t * DIN);
    const float4* c40 = reinterpret_cast<const float4*>(cw);
    const float4* c41 = reinterpret_cast<const float4*>(cw + DIN);
    const float4* c42 = reinterpret_cast<const float4*>(cw + 2 * DIN);
    float at = 0.f, a0 = 0.f, a1 = 0.f, a2 = 0.f;
#pragma unroll
    for (int j = 0; j < 8; j++) {
        int i = lane + 32 * j;
        float4 h = h4[i];
        float4 w = w4[i];
        at += h.x * w.x + h.y * w.y + h.z * w.z + h.w * w.w;
        float4 q = c40[i]; a0 += h.x * q.x + h.y * q.y + h.z * q.z + h.w * q.w;
        q = c41[i];        a1 += h.x * q.x + h.y * q.y + h.z * q.z + h.w * q.w;
        q = c42[i];        a2 += h.x * q.x + h.y * q.y + h.z * q.z + h.w * q.w;
    }
#pragma unroll
    for (int o = 16; o > 0; o >>= 1) {
        at += __shfl_xor_sync(0xffffffffu, at, o);
        a0 += __shfl_xor_sync(0xffffffffu, a0, o);
        a1 += __shfl_xor_sync(0xffffffffu, a1, o);
        a2 += __shfl_xor_sync(0xffffffffu, a2, o);
    }
    if (lane == 0) {
        g_tlogit[gw] = at + bias[t];
        g_clogit[gw][0] = a0 + cb[0];
        g_clogit[gw][1] = a1 + cb[1];
        g_clogit[gw][2] = a2 + cb[2];
        int r = (t < 20000) ? 0 : (t < 40000) ? 1 : (t < 200000) ? 2 : 3;
        g_cid[gw] = r;
        if (r > 0) {
            int idx = atomicAdd(&g_count[r], 1);
            g_list[r][idx] = gw;
        }
    }
}

// ---------------- store one chunk's regs into bf16 swizzled smem ----------------
__device__ __forceinline__ void store_tile(char* smem, int buf, int lrow, int lhalf,
                                           const float4 ar[8], const float4 br[8]) {
#pragma unroll
    for (int jj = 0; jj < 4; jj++) {
        uint4 v;
        v.x = pack_bf16(ar[2*jj].x,   ar[2*jj].y);
        v.y = pack_bf16(ar[2*jj].z,   ar[2*jj].w);
        v.z = pack_bf16(ar[2*jj+1].x, ar[2*jj+1].y);
        v.w = pack_bf16(ar[2*jj+1].z, ar[2*jj+1].w);
        uint32_t off = (uint32_t)(lrow * 128 + lhalf * 64 + jj * 16);
        *reinterpret_cast<uint4*>(smem + SA(buf) + SW(off)) = v;
    }
#pragma unroll
    for (int jj = 0; jj < 4; jj++) {
        uint4 v;
        v.x = pack_bf16(br[2*jj].x,   br[2*jj].y);
        v.y = pack_bf16(br[2*jj].z,   br[2*jj].w);
        v.z = pack_bf16(br[2*jj+1].x, br[2*jj+1].y);
        v.w = pack_bf16(br[2*jj+1].z, br[2*jj+1].w);
        uint32_t off = (uint32_t)(lrow * 128 + lhalf * 64 + jj * 16);
        *reinterpret_cast<uint4*>(smem + SB(buf) + SW(off)) = v;
    }
}

// ---------------- kernel 2: bf16 HMMA GEMM + sum-of-exp epilogue ----------------
__global__ __launch_bounds__(GT, 1)
void gemm_sumexp(const float* __restrict__ hidden,
                 const float* __restrict__ weight,
                 const float* __restrict__ bias,
                 int region, int lo, int width) {
    extern __shared__ char smem[];
    const int tid = threadIdx.x;
    const int count = g_count[region];
    const int row0 = blockIdx.x * TM;        // M-tiles fastest -> weight-tile sharers concurrent
    if (row0 >= count) return;
    const int col0 = blockIdx.y * TN;
    const uint32_t sb = smem_u32(smem);

    if (tid < TM) {
        int rr = row0 + tid;
        if (rr > count - 1) rr = count - 1;
        reinterpret_cast<int*>(smem + SLIST)[tid] = g_list[region][rr];
        reinterpret_cast<float*>(smem + SROW)[tid] = 0.0f;
    }
    if (tid < TN) {
        int cls = col0 + tid;
        reinterpret_cast<float*>(smem + SBIAS)[tid] =
            (cls < width) ? bias[lo + cls] : __int_as_float(0xff800000);  // -inf
    }
    __syncthreads();

    const int* listp = reinterpret_cast<const int*>(smem + SLIST);
    const int lrow = tid >> 1, lhalf = tid & 1;
    const float4* aptr = reinterpret_cast<const float4*>(
        hidden + (size_t)listp[lrow] * DIN + lhalf * 32);
    const int bcls = col0 + lrow;
    const bool bval = (bcls < width);
    const float4* bptr = reinterpret_cast<const float4*>(
        weight + (size_t)(lo + (bval ? bcls : width - 1)) * DIN + lhalf * 32);

    const int lane = tid & 31, wid = tid >> 5;
    const int wm = wid & 1, wn = wid >> 1;      // 2 M-warps x 4 N-warps

    float acc[4][4][4];
#pragma unroll
    for (int mi = 0; mi < 4; mi++)
#pragma unroll
        for (int nj = 0; nj < 4; nj++)
#pragma unroll
            for (int e = 0; e < 4; e++) acc[mi][nj][e] = 0.0f;

    float4 ar[8], br[8];
    const float4 z4 = make_float4(0.f, 0.f, 0.f, 0.f);
#pragma unroll
    for (int j = 0; j < 8; j++) ar[j] = aptr[j];
#pragma unroll
    for (int j = 0; j < 8; j++) br[j] = bval ? bptr[j] : z4;
    store_tile(smem, 0, lrow, lhalf, ar, br);
    __syncthreads();

    for (int kc = 0; kc < NKC; kc++) {
        const int cur = kc & 1;
        if (kc + 1 < NKC) {                    // prefetch next chunk into regs
#pragma unroll
            for (int j = 0; j < 8; j++) ar[j] = aptr[(kc + 1) * 16 + j];
#pragma unroll
            for (int j = 0; j < 8; j++) br[j] = bval ? bptr[(kc + 1) * 16 + j] : z4;
        }
#pragma unroll
        for (int ks = 0; ks < 4; ks++) {       // 4 x k16 per chunk
            uint32_t af[4][4];
#pragma unroll
            for (int mi = 0; mi < 4; mi++) {
                int r  = wm * 64 + mi * 16 + (lane & 15);
                int kb = ks * 16 + ((lane >> 4) << 3);
                uint32_t off = (uint32_t)(r * 128 + kb * 2);
                lds_frag4(af[mi], sb + SA(cur) + SW(off));
            }
            uint32_t bf[2][4];
#pragma unroll
            for (int np = 0; np < 2; np++) {
                int cl = wn * 32 + np * 16 + (lane & 7) + ((lane & 16) ? 8 : 0);
                int kb = ks * 16 + ((lane & 8) ? 8 : 0);
                uint32_t off = (uint32_t)(cl * 128 + kb * 2);
                lds_frag4(bf[np], sb + SB(cur) + SW(off));
            }
#pragma unroll
            for (int mi = 0; mi < 4; mi++)
#pragma unroll
                for (int nj = 0; nj < 4; nj++)
                    mma16816(acc[mi][nj], af[mi],
                             bf[nj >> 1][(nj & 1) * 2], bf[nj >> 1][(nj & 1) * 2 + 1]);
        }
        if (kc + 1 < NKC) store_tile(smem, cur ^ 1, lrow, lhalf, ar, br);
        __syncthreads();
    }

    // ---- epilogue: exp(logit + bias), reduce to per-row sums ----
    const float* bs = reinterpret_cast<const float*>(smem + SBIAS);
    float* rowsum = reinterpret_cast<float*>(smem + SROW);
    float loc[8];
#pragma unroll
    for (int i = 0; i < 8; i++) loc[i] = 0.0f;
#pragma unroll
    for (int mi = 0; mi < 4; mi++) {
#pragma unroll
        for (int nj = 0; nj < 4; nj++) {
            int c = wn * 32 + nj * 8 + 2 * (lane & 3);
            float b0 = bs[c], b1 = bs[c + 1];
            loc[2*mi]   += __expf(acc[mi][nj][0] + b0) + __expf(acc[mi][nj][1] + b1);
            loc[2*mi+1] += __expf(acc[mi][nj][2] + b0) + __expf(acc[mi][nj][3] + b1);
        }
    }
#pragma unroll
    for (int i = 0; i < 8; i++) {
        loc[i] += __shfl_xor_sync(0xffffffffu, loc[i], 1);
        loc[i] += __shfl_xor_sync(0xffffffffu, loc[i], 2);
    }
    if ((lane & 3) == 0) {
        int g = lane >> 2;
#pragma unroll
        for (int mi = 0; mi < 4; mi++) {
            atomicAdd(&rowsum[wm * 64 + mi * 16 + g],     loc[2*mi]);
            atomicAdd(&rowsum[wm * 64 + mi * 16 + g + 8], loc[2*mi+1]);
        }
    }
    __syncthreads();
    if (tid < TM && row0 + tid < count)
        atomicAdd(&g_S[region][listp[tid]], rowsum[tid]);
}

// ---------------- kernel 3: finalize NLL ----------------
__global__ void finalize_kernel(float* __restrict__ out) {
    int t = blockIdx.x * blockDim.x + threadIdx.x;
    if (t >= NTOK) return;
    int r = g_cid[t];
    float ch = __expf(g_clogit[t][0]) + __expf(g_clogit[t][1]) + __expf(g_clogit[t][2]);
    float lse_head = __logf(g_S[0][t] + ch);
    float nll;
    if (r == 0) {
        nll = lse_head - g_tlogit[t];
    } else {
        float lse_tail = __logf(g_S[r][t]);
        // reference: head_logprob[:, -i] for region i -> cluster column (3 - i)
        nll = lse_head + lse_tail - g_clogit[t][3 - r] - g_tlogit[t];
    }
    out[t] = nll;
}

// ---------------- launcher ----------------
extern "C" void kernel_launch(void* const* d_in, const int* in_sizes, int n_in,
                              void* d_out, int out_size) {
    const float* hidden = (const float*)d_in[0];
    const int*   target = (const int*)d_in[1];
    const float* weight = (const float*)d_in[2];
    const float* bias   = (const float*)d_in[3];
    const float* cw     = (const float*)d_in[4];
    const float* cb     = (const float*)d_in[5];
    float* out = (float*)d_out;

    cudaFuncSetAttribute(gemm_sumexp,
                         cudaFuncAttributeMaxDynamicSharedMemorySize, SMEM_TOTAL);

    zero_kernel<<<1, 256>>>();
    prep_kernel<<<128, 256>>>(hidden, target, weight, bias, cw, cb);

    // grid = (M-tiles, N-tiles); M fastest so weight-tile sharers are concurrent
    gemm_sumexp<<<dim3(8, 157),  GT, SMEM_TOTAL>>>(hidden, weight, bias, 0, 0,      20000);
    gemm_sumexp<<<dim3(8, 157),  GT, SMEM_TOTAL>>>(hidden, weight, bias, 1, 20000,  20000);
    gemm_sumexp<<<dim3(8, 1250), GT, SMEM_TOTAL>>>(hidden, weight, bias, 2, 40000,  160000);
    gemm_sumexp<<<dim3(8, 530),  GT, SMEM_TOTAL>>>(hidden, weight, bias, 3, 200000, 67735);

    finalize_kernel<<<4, 256>>>(out);
}

// round 5
// speedup vs baseline: 1.4909x; 1.4909x over previous
#include <cuda_runtime.h>
#include <cuda_bf16.h>
#include <cstdint>

// ---------------- problem constants ----------------
#define NTOK 1024
#define DIN  1024
// regions: [0,20000) head, [20000,40000), [40000,200000), [200000,267735)

// ---------------- GEMM tile config ----------------
#define TM 128
#define TN 128
#define KC 64
#define NKC 16              // DIN / KC
#define GT 512              // threads per CTA (16 warps, 4M x 4N)

// N-tile counts per region and cumulative offsets (classes / TN, ceil)
#define NT0 157
#define NT1 157
#define NT2 1250
#define NT3 530
#define NT_TOTAL (NT0 + NT1 + NT2 + NT3)   // 2094

// smem byte offsets (dynamic). Buffers 1024-aligned for SW128 swizzle atoms.
#define SA(buf) ((buf) * 16384)              // A: 2 x (128 rows x 128B)
#define SB(buf) (32768 + (buf) * 16384)      // B: 2 x (128 rows x 128B)
#define SBIAS 65536                          // 128 f32
#define SLIST 66048                          // 128 int
#define SROW  66560                          // 128 f32
#define SMEM_TOTAL 67072

#define SW(o) ((o) ^ (((o) >> 3) & 0x70))    // SW128 swizzle on byte offsets

// ---------------- device scratch (static; no allocation) ----------------
__device__ float g_S[4][NTOK];          // per-region per-token sum of exp
__device__ int   g_list[4][NTOK];       // compacted token lists
__device__ int   g_count[4];
__device__ float g_tlogit[NTOK];        // exact f32 target logit (incl bias)
__device__ float g_clogit[NTOK][3];     // exact f32 cluster logits (incl bias)
__device__ int   g_cid[NTOK];

// ---------------- small helpers ----------------
__device__ __forceinline__ uint32_t smem_u32(const void* p) {
    uint32_t a;
    asm("{ .reg .u64 t; cvta.to.shared.u64 t, %1; cvt.u32.u64 %0, t; }" : "=r"(a) : "l"(p));
    return a;
}
__device__ __forceinline__ uint32_t pack_bf16(float a, float b) {
    __nv_bfloat162 h = __floats2bfloat162_rn(a, b);
    return *reinterpret_cast<uint32_t*>(&h);
}
__device__ __forceinline__ void lds_frag4(uint32_t r[4], uint32_t addr) {
    asm volatile("ldmatrix.sync.aligned.m8n8.x4.shared.b16 {%0,%1,%2,%3}, [%4];"
        : "=r"(r[0]), "=r"(r[1]), "=r"(r[2]), "=r"(r[3]) : "r"(addr));
}
__device__ __forceinline__ void mma16816(float d[4], const uint32_t a[4],
                                         uint32_t b0, uint32_t b1) {
    asm volatile("mma.sync.aligned.m16n8k16.row.col.f32.bf16.bf16.f32 "
        "{%0,%1,%2,%3}, {%4,%5,%6,%7}, {%8,%9}, {%0,%1,%2,%3};"
        : "+f"(d[0]), "+f"(d[1]), "+f"(d[2]), "+f"(d[3])
        : "r"(a[0]), "r"(a[1]), "r"(a[2]), "r"(a[3]), "r"(b0), "r"(b1));
}

// ---------------- kernel 0: reset scratch ----------------
__global__ void zero_kernel() {
    int t = threadIdx.x;
    for (int i = t; i < 4 * NTOK; i += blockDim.x) (&g_S[0][0])[i] = 0.0f;
    for (int i = t; i < NTOK; i += blockDim.x) g_list[0][i] = i;
    if (t == 0) g_count[0] = NTOK;
    if (t >= 1 && t < 4) g_count[t] = 0;
}

// ---------------- kernel 1: per-token prep (exact f32 dots + compaction) ----------------
__global__ void prep_kernel(const float* __restrict__ hidden,
                            const int* __restrict__ target,   // int32 (JAX x64 disabled)
                            const float* __restrict__ weight,
                            const float* __restrict__ bias,
                            const float* __restrict__ cw,
                            const float* __restrict__ cb) {
    int gw = (int)((blockIdx.x * blockDim.x + threadIdx.x) >> 5);
    int lane = threadIdx.x & 31;
    if (gw >= NTOK) return;
    const int t = target[gw];
    const float4* h4  = reinterpret_cast<const float4*>(hidden + (size_t)gw * DIN);
    const float4* w4  = reinterpret_cast<const float4*>(weight + (size_t)t * DIN);
    const float4* c40 = reinterpret_cast<const float4*>(cw);
    const float4* c41 = reinterpret_cast<const float4*>(cw + DIN);
    const float4* c42 = reinterpret_cast<const float4*>(cw + 2 * DIN);
    float at = 0.f, a0 = 0.f, a1 = 0.f, a2 = 0.f;
#pragma unroll
    for (int j = 0; j < 8; j++) {
        int i = lane + 32 * j;
        float4 h = h4[i];
        float4 w = w4[i];
        at += h.x * w.x + h.y * w.y + h.z * w.z + h.w * w.w;
        float4 q = c40[i]; a0 += h.x * q.x + h.y * q.y + h.z * q.z + h.w * q.w;
        q = c41[i];        a1 += h.x * q.x + h.y * q.y + h.z * q.z + h.w * q.w;
        q = c42[i];        a2 += h.x * q.x + h.y * q.y + h.z * q.z + h.w * q.w;
    }
#pragma unroll
    for (int o = 16; o > 0; o >>= 1) {
        at += __shfl_xor_sync(0xffffffffu, at, o);
        a0 += __shfl_xor_sync(0xffffffffu, a0, o);
        a1 += __shfl_xor_sync(0xffffffffu, a1, o);
        a2 += __shfl_xor_sync(0xffffffffu, a2, o);
    }
    if (lane == 0) {
        g_tlogit[gw] = at + bias[t];
        g_clogit[gw][0] = a0 + cb[0];
        g_clogit[gw][1] = a1 + cb[1];
        g_clogit[gw][2] = a2 + cb[2];
        int r = (t < 20000) ? 0 : (t < 40000) ? 1 : (t < 200000) ? 2 : 3;
        g_cid[gw] = r;
        if (r > 0) {
            int idx = atomicAdd(&g_count[r], 1);
            g_list[r][idx] = gw;
        }
    }
}

// ---------------- store one chunk's regs into bf16 swizzled smem ----------------
// thread: row = tid>>2 (0..127), q = tid&3 covers 16 cols (2 x 16B swizzled stores per tile)
__device__ __forceinline__ void store_tile(char* smem, int buf, int row, int q,
                                           const float4 ar[4], const float4 br[4]) {
#pragma unroll
    for (int p = 0; p < 2; p++) {
        uint4 v;
        v.x = pack_bf16(ar[2*p].x,   ar[2*p].y);
        v.y = pack_bf16(ar[2*p].z,   ar[2*p].w);
        v.z = pack_bf16(ar[2*p+1].x, ar[2*p+1].y);
        v.w = pack_bf16(ar[2*p+1].z, ar[2*p+1].w);
        uint32_t off = (uint32_t)(row * 128 + q * 32 + p * 16);
        *reinterpret_cast<uint4*>(smem + SA(buf) + SW(off)) = v;
    }
#pragma unroll
    for (int p = 0; p < 2; p++) {
        uint4 v;
        v.x = pack_bf16(br[2*p].x,   br[2*p].y);
        v.y = pack_bf16(br[2*p].z,   br[2*p].w);
        v.z = pack_bf16(br[2*p+1].x, br[2*p+1].y);
        v.w = pack_bf16(br[2*p+1].z, br[2*p+1].w);
        uint32_t off = (uint32_t)(row * 128 + q * 32 + p * 16);
        *reinterpret_cast<uint4*>(smem + SB(buf) + SW(off)) = v;
    }
}

// ---------------- kernel 2: merged bf16 HMMA GEMM + sum-of-exp epilogue ----------------
__global__ __launch_bounds__(GT, 1)
void gemm_sumexp(const float* __restrict__ hidden,
                 const float* __restrict__ weight,
                 const float* __restrict__ bias) {
    extern __shared__ char smem[];
    const int tid = threadIdx.x;

    // region mapping from concatenated N-tile index
    int nt = blockIdx.y;
    int region, lo, width;
    if (nt < NT0)                  { region = 0; lo = 0;      width = 20000;  }
    else if (nt < NT0 + NT1)       { region = 1; lo = 20000;  width = 20000;  nt -= NT0; }
    else if (nt < NT0 + NT1 + NT2) { region = 2; lo = 40000;  width = 160000; nt -= NT0 + NT1; }
    else                           { region = 3; lo = 200000; width = 67735;  nt -= NT0 + NT1 + NT2; }

    const int count = g_count[region];
    const int row0 = blockIdx.x * TM;        // M fastest -> weight-tile sharers concurrent
    if (row0 >= count) return;
    const int col0 = nt * TN;
    const uint32_t sb = smem_u32(smem);

    if (tid < TM) {
        int rr = row0 + tid;
        if (rr > count - 1) rr = count - 1;
        reinterpret_cast<int*>(smem + SLIST)[tid] = g_list[region][rr];
        reinterpret_cast<float*>(smem + SROW)[tid] = 0.0f;
    }
    if (tid >= TM && tid < TM + TN) {
        int c = tid - TM;
        int cls = col0 + c;
        reinterpret_cast<float*>(smem + SBIAS)[c] =
            (cls < width) ? bias[lo + cls] : __int_as_float(0xff800000);  // -inf
    }
    __syncthreads();

    const int* listp = reinterpret_cast<const int*>(smem + SLIST);
    const int lrow = tid >> 2, q = tid & 3;          // 4 threads per row, 16 cols each
    const float4* aptr = reinterpret_cast<const float4*>(
        hidden + (size_t)listp[lrow] * DIN + q * 16);
    const int bcls = col0 + lrow;
    const bool bval = (bcls < width);
    const float4* bptr = reinterpret_cast<const float4*>(
        weight + (size_t)(lo + (bval ? bcls : width - 1)) * DIN + q * 16);

    const int lane = tid & 31, wid = tid >> 5;
    const int wm = wid & 3, wn = wid >> 2;           // 4 M-warps x 4 N-warps

    float acc[2][4][4];
#pragma unroll
    for (int mi = 0; mi < 2; mi++)
#pragma unroll
        for (int nj = 0; nj < 4; nj++)
#pragma unroll
            for (int e = 0; e < 4; e++) acc[mi][nj][e] = 0.0f;

    float4 ar[4], br[4];
    const float4 z4 = make_float4(0.f, 0.f, 0.f, 0.f);
#pragma unroll
    for (int j = 0; j < 4; j++) ar[j] = aptr[j];
#pragma unroll
    for (int j = 0; j < 4; j++) br[j] = bval ? bptr[j] : z4;
    store_tile(smem, 0, lrow, q, ar, br);
    __syncthreads();

    for (int kc = 0; kc < NKC; kc++) {
        const int cur = kc & 1;
        if (kc + 1 < NKC) {                    // prefetch next chunk into regs
#pragma unroll
            for (int j = 0; j < 4; j++) ar[j] = aptr[(kc + 1) * 16 + j];
#pragma unroll
            for (int j = 0; j < 4; j++) br[j] = bval ? bptr[(kc + 1) * 16 + j] : z4;
        }
#pragma unroll
        for (int ks = 0; ks < 4; ks++) {       // 4 x k16 per chunk
            uint32_t af[2][4];
#pragma unroll
            for (int mi = 0; mi < 2; mi++) {
                int r  = wm * 32 + mi * 16 + (lane & 15);
                int kb = ks * 16 + ((lane >> 4) << 3);
                uint32_t off = (uint32_t)(r * 128 + kb * 2);
                lds_frag4(af[mi], sb + SA(cur) + SW(off));
            }
            uint32_t bf[2][4];
#pragma unroll
            for (int np = 0; np < 2; np++) {
                int cl = wn * 32 + np * 16 + (lane & 7) + ((lane & 16) ? 8 : 0);
                int kb = ks * 16 + ((lane & 8) ? 8 : 0);
                uint32_t off = (uint32_t)(cl * 128 + kb * 2);
                lds_frag4(bf[np], sb + SB(cur) + SW(off));
            }
#pragma unroll
            for (int mi = 0; mi < 2; mi++)
#pragma unroll
                for (int nj = 0; nj < 4; nj++)
                    mma16816(acc[mi][nj], af[mi],
                             bf[nj >> 1][(nj & 1) * 2], bf[nj >> 1][(nj & 1) * 2 + 1]);
        }
        if (kc + 1 < NKC) store_tile(smem, cur ^ 1, lrow, q, ar, br);
        __syncthreads();
    }

    // ---- epilogue: exp(logit + bias), reduce to per-row sums ----
    const float* bs = reinterpret_cast<const float*>(smem + SBIAS);
    float* rowsum = reinterpret_cast<float*>(smem + SROW);
    float loc[4];
#pragma unroll
    for (int i = 0; i < 4; i++) loc[i] = 0.0f;
#pragma unroll
    for (int mi = 0; mi < 2; mi++) {
#pragma unroll
        for (int nj = 0; nj < 4; nj++) {
            int c = wn * 32 + nj * 8 + 2 * (lane & 3);
            float b0 = bs[c], b1 = bs[c + 1];
            loc[2*mi]   += __expf(acc[mi][nj][0] + b0) + __expf(acc[mi][nj][1] + b1);
            loc[2*mi+1] += __expf(acc[mi][nj][2] + b0) + __expf(acc[mi][nj][3] + b1);
        }
    }
#pragma unroll
    for (int i = 0; i < 4; i++) {
        loc[i] += __shfl_xor_sync(0xffffffffu, loc[i], 1);
        loc[i] += __shfl_xor_sync(0xffffffffu, loc[i], 2);
    }
    if ((lane & 3) == 0) {
        int g = lane >> 2;
#pragma unroll
        for (int mi = 0; mi < 2; mi++) {
            atomicAdd(&rowsum[wm * 32 + mi * 16 + g],     loc[2*mi]);
            atomicAdd(&rowsum[wm * 32 + mi * 16 + g + 8], loc[2*mi+1]);
        }
    }
    __syncthreads();
    if (tid < TM && row0 + tid < count)
        atomicAdd(&g_S[region][listp[tid]], rowsum[tid]);
}

// ---------------- kernel 3: finalize NLL ----------------
__global__ void finalize_kernel(float* __restrict__ out) {
    int t = blockIdx.x * blockDim.x + threadIdx.x;
    if (t >= NTOK) return;
    int r = g_cid[t];
    float ch = __expf(g_clogit[t][0]) + __expf(g_clogit[t][1]) + __expf(g_clogit[t][2]);
    float lse_head = __logf(g_S[0][t] + ch);
    float nll;
    if (r == 0) {
        nll = lse_head - g_tlogit[t];
    } else {
        float lse_tail = __logf(g_S[r][t]);
        // reference: head_logprob[:, -i] for region i -> cluster column (3 - i)
        nll = lse_head + lse_tail - g_clogit[t][3 - r] - g_tlogit[t];
    }
    out[t] = nll;
}

// ---------------- launcher ----------------
extern "C" void kernel_launch(void* const* d_in, const int* in_sizes, int n_in,
                              void* d_out, int out_size) {
    const float* hidden = (const float*)d_in[0];
    const int*   target = (const int*)d_in[1];
    const float* weight = (const float*)d_in[2];
    const float* bias   = (const float*)d_in[3];
    const float* cw     = (const float*)d_in[4];
    const float* cb     = (const float*)d_in[5];
    float* out = (float*)d_out;

    cudaFuncSetAttribute(gemm_sumexp,
                         cudaFuncAttributeMaxDynamicSharedMemorySize, SMEM_TOTAL);

    zero_kernel<<<1, 256>>>();
    prep_kernel<<<128, 256>>>(hidden, target, weight, bias, cw, cb);

    // one merged launch over all regions; M-tiles fastest
    gemm_sumexp<<<dim3(8, NT_TOTAL), GT, SMEM_TOTAL>>>(hidden, weight, bias);

    finalize_kernel<<<4, 256>>>(out);
}

// round 6
// speedup vs baseline: 2.3640x; 1.5856x over previous
#include <cuda_runtime.h>
#include <cuda_bf16.h>
#include <cstdint>

// ---------------- problem constants ----------------
#define NTOK 1024
#define DIN  1024
// regions: [0,20000) head, [20000,40000), [40000,200000), [200000,267735)

// ---------------- GEMM tile config ----------------
#define TM 128
#define TN 128
#define KC 64
#define NKC 16              // DIN / KC
#define GT 512              // threads per CTA (16 warps, 4M x 4N)

// N-tile counts per region (classes / TN, ceil)
#define NT0 157
#define NT1 157
#define NT2 1250
#define NT3 530
#define NT_TOTAL (NT0 + NT1 + NT2 + NT3)   // 2094

// smem byte offsets (dynamic). Buffers 1024-aligned for SW128 swizzle atoms.
#define SA(buf) ((buf) * 16384)              // A: 2 x (128 rows x 128B)
#define SB(buf) (32768 + (buf) * 16384)      // B: 2 x (128 rows x 128B)
#define SBIAS 65536                          // 128 f32
#define SLIST 66048                          // 128 int
#define SROW  66560                          // 128 f32
#define SMEM_TOTAL 67072

#define SW(o) ((o) ^ (((o) >> 3) & 0x70))    // SW128 swizzle on byte offsets

// ---------------- device scratch (static; no allocation) ----------------
__device__ float g_S[4][NTOK];          // per-region per-token sum of exp
__device__ int   g_list[4][NTOK];       // compacted token lists
__device__ int   g_count[4];
__device__ float g_tlogit[NTOK];        // exact f32 target logit (incl bias)
__device__ float g_clogit[NTOK][3];     // exact f32 cluster logits (incl bias)
__device__ int   g_cid[NTOK];

// ---------------- small helpers ----------------
__device__ __forceinline__ uint32_t smem_u32(const void* p) {
    uint32_t a;
    asm("{ .reg .u64 t; cvta.to.shared.u64 t, %1; cvt.u32.u64 %0, t; }" : "=r"(a) : "l"(p));
    return a;
}
__device__ __forceinline__ uint32_t pack_bf16(float a, float b) {
    __nv_bfloat162 h = __floats2bfloat162_rn(a, b);
    return *reinterpret_cast<uint32_t*>(&h);
}
__device__ __forceinline__ void lds_frag4(uint32_t r[4], uint32_t addr) {
    asm volatile("ldmatrix.sync.aligned.m8n8.x4.shared.b16 {%0,%1,%2,%3}, [%4];"
        : "=r"(r[0]), "=r"(r[1]), "=r"(r[2]), "=r"(r[3]) : "r"(addr));
}
__device__ __forceinline__ void mma16816(float d[4], const uint32_t a[4],
                                         uint32_t b0, uint32_t b1) {
    asm volatile("mma.sync.aligned.m16n8k16.row.col.f32.bf16.bf16.f32 "
        "{%0,%1,%2,%3}, {%4,%5,%6,%7}, {%8,%9}, {%0,%1,%2,%3};"
        : "+f"(d[0]), "+f"(d[1]), "+f"(d[2]), "+f"(d[3])
        : "r"(a[0]), "r"(a[1]), "r"(a[2]), "r"(a[3]), "r"(b0), "r"(b1));
}

// ---------------- kernel 0: reset scratch ----------------
__global__ void zero_kernel() {
    int t = threadIdx.x;
    for (int i = t; i < 4 * NTOK; i += blockDim.x) (&g_S[0][0])[i] = 0.0f;
    for (int i = t; i < NTOK; i += blockDim.x) g_list[0][i] = i;
    if (t == 0) g_count[0] = NTOK;
    if (t >= 1 && t < 4) g_count[t] = 0;
}

// ---------------- kernel 1: per-token prep (exact f32 dots + compaction) ----------------
__global__ void prep_kernel(const float* __restrict__ hidden,
                            const int* __restrict__ target,   // int32 (JAX x64 disabled)
                            const float* __restrict__ weight,
                            const float* __restrict__ bias,
                            const float* __restrict__ cw,
                            const float* __restrict__ cb) {
    int gw = (int)((blockIdx.x * blockDim.x + threadIdx.x) >> 5);
    int lane = threadIdx.x & 31;
    if (gw >= NTOK) return;
    const int t = target[gw];
    const float4* h4  = reinterpret_cast<const float4*>(hidden + (size_t)gw * DIN);
    const float4* w4  = reinterpret_cast<const float4*>(weight + (size_t)t * DIN);
    const float4* c40 = reinterpret_cast<const float4*>(cw);
    const float4* c41 = reinterpret_cast<const float4*>(cw + DIN);
    const float4* c42 = reinterpret_cast<const float4*>(cw + 2 * DIN);
    float at = 0.f, a0 = 0.f, a1 = 0.f, a2 = 0.f;
#pragma unroll
    for (int j = 0; j < 8; j++) {
        int i = lane + 32 * j;
        float4 h = h4[i];
        float4 w = w4[i];
        at += h.x * w.x + h.y * w.y + h.z * w.z + h.w * w.w;
        float4 q = c40[i]; a0 += h.x * q.x + h.y * q.y + h.z * q.z + h.w * q.w;
        q = c41[i];        a1 += h.x * q.x + h.y * q.y + h.z * q.z + h.w * q.w;
        q = c42[i];        a2 += h.x * q.x + h.y * q.y + h.z * q.z + h.w * q.w;
    }
#pragma unroll
    for (int o = 16; o > 0; o >>= 1) {
        at += __shfl_xor_sync(0xffffffffu, at, o);
        a0 += __shfl_xor_sync(0xffffffffu, a0, o);
        a1 += __shfl_xor_sync(0xffffffffu, a1, o);
        a2 += __shfl_xor_sync(0xffffffffu, a2, o);
    }
    if (lane == 0) {
        g_tlogit[gw] = at + bias[t];
        g_clogit[gw][0] = a0 + cb[0];
        g_clogit[gw][1] = a1 + cb[1];
        g_clogit[gw][2] = a2 + cb[2];
        int r = (t < 20000) ? 0 : (t < 40000) ? 1 : (t < 200000) ? 2 : 3;
        g_cid[gw] = r;
        if (r > 0) {
            int idx = atomicAdd(&g_count[r], 1);
            g_list[r][idx] = gw;
        }
    }
}

// ---------------- kernel 2: merged bf16 HMMA GEMM + sum-of-exp epilogue ----------------
// Global-load mapping (coalesced): warp w owns rows [w*8, w*8+8).
// Per LDG instruction j: lanes 0-15 -> row w*8+j*2,   bytes (lane&15)*16 of the 256B chunk
//                        lanes 16-31 -> row w*8+j*2+1, same bytes
// => each warp-LDG covers 2 rows x 256B = 4 fully-used 128B lines (4 L1 wavefronts).
__global__ __launch_bounds__(GT, 1)
void gemm_sumexp(const float* __restrict__ hidden,
                 const float* __restrict__ weight,
                 const float* __restrict__ bias) {
    extern __shared__ char smem[];
    const int tid = threadIdx.x;

    // region mapping from concatenated N-tile index
    int nt = blockIdx.y;
    int region, lo, width;
    if (nt < NT0)                  { region = 0; lo = 0;      width = 20000;  }
    else if (nt < NT0 + NT1)       { region = 1; lo = 20000;  width = 20000;  nt -= NT0; }
    else if (nt < NT0 + NT1 + NT2) { region = 2; lo = 40000;  width = 160000; nt -= NT0 + NT1; }
    else                           { region = 3; lo = 200000; width = 67735;  nt -= NT0 + NT1 + NT2; }

    const int count = g_count[region];
    const int row0 = blockIdx.x * TM;        // M fastest -> weight-tile sharers concurrent
    if (row0 >= count) return;
    const int col0 = nt * TN;
    const uint32_t sb = smem_u32(smem);

    if (tid < TM) {
        int rr = row0 + tid;
        if (rr > count - 1) rr = count - 1;
        reinterpret_cast<int*>(smem + SLIST)[tid] = g_list[region][rr];
        reinterpret_cast<float*>(smem + SROW)[tid] = 0.0f;
    }
    if (tid >= TM && tid < TM + TN) {
        int c = tid - TM;
        int cls = col0 + c;
        reinterpret_cast<float*>(smem + SBIAS)[c] =
            (cls < width) ? bias[lo + cls] : __int_as_float(0xff800000);  // -inf
    }
    __syncthreads();

    const int* listp = reinterpret_cast<const int*>(smem + SLIST);
    const int lane = tid & 31, wid = tid >> 5;
    const int half = lane >> 4;              // 0/1: which row of the pair
    const int pos  = lane & 15;              // 16B unit within the 256B chunk

    // per-thread rows are chunk-invariant: precompute base pointers + smem offsets
    const float* aptr[4];
    const float* bptr[4];
    bool bvalid[4];
    uint32_t soff[4];
#pragma unroll
    for (int j = 0; j < 4; j++) {
        int r = wid * 8 + j * 2 + half;      // 0..127
        aptr[j] = hidden + (size_t)listp[r] * DIN + pos * 4;
        int cls = col0 + r;
        bvalid[j] = (cls < width);
        bptr[j] = weight + (size_t)(lo + (bvalid[j] ? cls : width - 1)) * DIN + pos * 4;
        uint32_t o = (uint32_t)(r * 128 + pos * 8);   // bf16 row = 128B
        soff[j] = SW(o);
    }

    const int wm = wid & 3, wn = wid >> 2;   // 4 M-warps x 4 N-warps

    float acc[2][4][4];
#pragma unroll
    for (int mi = 0; mi < 2; mi++)
#pragma unroll
        for (int nj = 0; nj < 4; nj++)
#pragma unroll
            for (int e = 0; e < 4; e++) acc[mi][nj][e] = 0.0f;

    float4 ar[4], br[4];
    const float4 z4 = make_float4(0.f, 0.f, 0.f, 0.f);
#pragma unroll
    for (int j = 0; j < 4; j++) ar[j] = *reinterpret_cast<const float4*>(aptr[j]);
#pragma unroll
    for (int j = 0; j < 4; j++) br[j] = bvalid[j] ? *reinterpret_cast<const float4*>(bptr[j]) : z4;

    // store chunk 0
#pragma unroll
    for (int j = 0; j < 4; j++) {
        uint2 va = make_uint2(pack_bf16(ar[j].x, ar[j].y), pack_bf16(ar[j].z, ar[j].w));
        uint2 vb = make_uint2(pack_bf16(br[j].x, br[j].y), pack_bf16(br[j].z, br[j].w));
        *reinterpret_cast<uint2*>(smem + SA(0) + soff[j]) = va;
        *reinterpret_cast<uint2*>(smem + SB(0) + soff[j]) = vb;
    }
    __syncthreads();

    for (int kc = 0; kc < NKC; kc++) {
        const int cur = kc & 1;
        if (kc + 1 < NKC) {                    // prefetch next chunk into regs
#pragma unroll
            for (int j = 0; j < 4; j++)
                ar[j] = *reinterpret_cast<const float4*>(aptr[j] + (kc + 1) * KC);
#pragma unroll
            for (int j = 0; j < 4; j++)
                br[j] = bvalid[j] ? *reinterpret_cast<const float4*>(bptr[j] + (kc + 1) * KC) : z4;
        }
#pragma unroll
        for (int ks = 0; ks < 4; ks++) {       // 4 x k16 per chunk
            uint32_t af[2][4];
#pragma unroll
            for (int mi = 0; mi < 2; mi++) {
                int r  = wm * 32 + mi * 16 + (lane & 15);
                int kb = ks * 16 + ((lane >> 4) << 3);
                uint32_t off = (uint32_t)(r * 128 + kb * 2);
                lds_frag4(af[mi], sb + SA(cur) + SW(off));
            }
            uint32_t bf[2][4];
#pragma unroll
            for (int np = 0; np < 2; np++) {
                int cl = wn * 32 + np * 16 + (lane & 7) + ((lane & 16) ? 8 : 0);
                int kb = ks * 16 + ((lane & 8) ? 8 : 0);
                uint32_t off = (uint32_t)(cl * 128 + kb * 2);
                lds_frag4(bf[np], sb + SB(cur) + SW(off));
            }
#pragma unroll
            for (int mi = 0; mi < 2; mi++)
#pragma unroll
                for (int nj = 0; nj < 4; nj++)
                    mma16816(acc[mi][nj], af[mi],
                             bf[nj >> 1][(nj & 1) * 2], bf[nj >> 1][(nj & 1) * 2 + 1]);
        }
        if (kc + 1 < NKC) {
            const int nxt = cur ^ 1;
#pragma unroll
            for (int j = 0; j < 4; j++) {
                uint2 va = make_uint2(pack_bf16(ar[j].x, ar[j].y), pack_bf16(ar[j].z, ar[j].w));
                uint2 vb = make_uint2(pack_bf16(br[j].x, br[j].y), pack_bf16(br[j].z, br[j].w));
                *reinterpret_cast<uint2*>(smem + SA(nxt) + soff[j]) = va;
                *reinterpret_cast<uint2*>(smem + SB(nxt) + soff[j]) = vb;
            }
        }
        __syncthreads();
    }

    // ---- epilogue: exp(logit + bias), reduce to per-row sums ----
    const float* bs = reinterpret_cast<const float*>(smem + SBIAS);
    float* rowsum = reinterpret_cast<float*>(smem + SROW);
    float loc[4];
#pragma unroll
    for (int i = 0; i < 4; i++) loc[i] = 0.0f;
#pragma unroll
    for (int mi = 0; mi < 2; mi++) {
#pragma unroll
        for (int nj = 0; nj < 4; nj++) {
            int c = wn * 32 + nj * 8 + 2 * (lane & 3);
            float b0 = bs[c], b1 = bs[c + 1];
            loc[2*mi]   += __expf(acc[mi][nj][0] + b0) + __expf(acc[mi][nj][1] + b1);
            loc[2*mi+1] += __expf(acc[mi][nj][2] + b0) + __expf(acc[mi][nj][3] + b1);
        }
    }
#pragma unroll
    for (int i = 0; i < 4; i++) {
        loc[i] += __shfl_xor_sync(0xffffffffu, loc[i], 1);
        loc[i] += __shfl_xor_sync(0xffffffffu, loc[i], 2);
    }
    if ((lane & 3) == 0) {
        int g = lane >> 2;
#pragma unroll
        for (int mi = 0; mi < 2; mi++) {
            atomicAdd(&rowsum[wm * 32 + mi * 16 + g],     loc[2*mi]);
            atomicAdd(&rowsum[wm * 32 + mi * 16 + g + 8], loc[2*mi+1]);
        }
    }
    __syncthreads();
    if (tid < TM && row0 + tid < count)
        atomicAdd(&g_S[region][listp[tid]], rowsum[tid]);
}

// ---------------- kernel 3: finalize NLL ----------------
__global__ void finalize_kernel(float* __restrict__ out) {
    int t = blockIdx.x * blockDim.x + threadIdx.x;
    if (t >= NTOK) return;
    int r = g_cid[t];
    float ch = __expf(g_clogit[t][0]) + __expf(g_clogit[t][1]) + __expf(g_clogit[t][2]);
    float lse_head = __logf(g_S[0][t] + ch);
    float nll;
    if (r == 0) {
        nll = lse_head - g_tlogit[t];
    } else {
        float lse_tail = __logf(g_S[r][t]);
        // reference: head_logprob[:, -i] for region i -> cluster column (3 - i)
        nll = lse_head + lse_tail - g_clogit[t][3 - r] - g_tlogit[t];
    }
    out[t] = nll;
}

// ---------------- launcher ----------------
extern "C" void kernel_launch(void* const* d_in, const int* in_sizes, int n_in,
                              void* d_out, int out_size) {
    const float* hidden = (const float*)d_in[0];
    const int*   target = (const int*)d_in[1];
    const float* weight = (const float*)d_in[2];
    const float* bias   = (const float*)d_in[3];
    const float* cw     = (const float*)d_in[4];
    const float* cb     = (const float*)d_in[5];
    float* out = (float*)d_out;

    cudaFuncSetAttribute(gemm_sumexp,
                         cudaFuncAttributeMaxDynamicSharedMemorySize, SMEM_TOTAL);

    zero_kernel<<<1, 256>>>();
    prep_kernel<<<128, 256>>>(hidden, target, weight, bias, cw, cb);

    // one merged launch over all regions; M-tiles fastest
    gemm_sumexp<<<dim3(8, NT_TOTAL), GT, SMEM_TOTAL>>>(hidden, weight, bias);

    finalize_kernel<<<4, 256>>>(out);
}

// round 7
// speedup vs baseline: 2.8601x; 1.2098x over previous
#include <cuda_runtime.h>
#include <cuda_bf16.h>
#include <cstdint>

// ---------------- problem constants ----------------
#define NTOK 1024
#define DIN  1024
#define NCLS 267735
#define WELEMS ((size_t)NCLS * DIN)          // 274,160,640
// regions: [0,20000) head, [20000,40000), [40000,200000), [200000,267735)

// ---------------- GEMM tile config ----------------
#define TM 128
#define TN 256
#define KC 64
#define NKC 16              // DIN / KC
#define GT 256              // 8 warps: 2 M-warps x 4 N-warps, warp tile 64x64

// N-tile counts per region (classes / TN, ceil)
#define NT0 79
#define NT1 79
#define NT2 625
#define NT3 265
#define NT_TOTAL (NT0 + NT1 + NT2 + NT3)   // 1048

// smem byte offsets. A: 2 x 16KB, B: 2 x 32KB (bf16, 128B rows, SW128)
#define SA(buf) ((buf) * 16384)
#define SB(buf) (32768 + (buf) * 32768)
#define SBIAS 98304                          // 256 f32
#define SLIST 99328                          // 128 int
#define SROW  99840                          // 128 f32
#define SMEM_TOTAL 100352

#define SW(o) ((o) ^ (((o) >> 3) & 0x70))    // SW128 swizzle on byte offsets

// ---------------- device scratch (static; no allocation) ----------------
__device__ __nv_bfloat16 g_wbf[WELEMS];      // bf16 weight (548 MB)
__device__ __nv_bfloat16 g_hbf[NTOK * DIN];  // bf16 hidden
__device__ float g_S[4][NTOK];
__device__ int   g_list[4][NTOK];
__device__ int   g_count[4];
__device__ float g_tlogit[NTOK];
__device__ float g_clogit[NTOK][3];
__device__ int   g_cid[NTOK];

// ---------------- small helpers ----------------
__device__ __forceinline__ uint32_t smem_u32(const void* p) {
    uint32_t a;
    asm("{ .reg .u64 t; cvta.to.shared.u64 t, %1; cvt.u32.u64 %0, t; }" : "=r"(a) : "l"(p));
    return a;
}
__device__ __forceinline__ uint32_t pack_bf16(float a, float b) {
    __nv_bfloat162 h = __floats2bfloat162_rn(a, b);
    return *reinterpret_cast<uint32_t*>(&h);
}
__device__ __forceinline__ void lds_frag4(uint32_t r[4], uint32_t addr) {
    asm volatile("ldmatrix.sync.aligned.m8n8.x4.shared.b16 {%0,%1,%2,%3}, [%4];"
        : "=r"(r[0]), "=r"(r[1]), "=r"(r[2]), "=r"(r[3]) : "r"(addr));
}
__device__ __forceinline__ void mma16816(float d[4], const uint32_t a[4],
                                         uint32_t b0, uint32_t b1) {
    asm volatile("mma.sync.aligned.m16n8k16.row.col.f32.bf16.bf16.f32 "
        "{%0,%1,%2,%3}, {%4,%5,%6,%7}, {%8,%9}, {%0,%1,%2,%3};"
        : "+f"(d[0]), "+f"(d[1]), "+f"(d[2]), "+f"(d[3])
        : "r"(a[0]), "r"(a[1]), "r"(a[2]), "r"(a[3]), "r"(b0), "r"(b1));
}

// ---------------- kernel 0: reset scratch ----------------
__global__ void zero_kernel() {
    int t = threadIdx.x;
    for (int i = t; i < 4 * NTOK; i += blockDim.x) (&g_S[0][0])[i] = 0.0f;
    for (int i = t; i < NTOK; i += blockDim.x) g_list[0][i] = i;
    if (t == 0) g_count[0] = NTOK;
    if (t >= 1 && t < 4) g_count[t] = 0;
}

// ---------------- f32 -> bf16 streaming convert (8 elems / thread) ----------------
__global__ void convert_kernel(const float* __restrict__ src,
                               __nv_bfloat16* __restrict__ dst, size_t n8) {
    size_t i = (size_t)blockIdx.x * blockDim.x + threadIdx.x;
    if (i >= n8) return;
    const float4* p = reinterpret_cast<const float4*>(src) + i * 2;
    float4 a = p[0], b = p[1];
    uint4 o;
    o.x = pack_bf16(a.x, a.y); o.y = pack_bf16(a.z, a.w);
    o.z = pack_bf16(b.x, b.y); o.w = pack_bf16(b.z, b.w);
    reinterpret_cast<uint4*>(dst)[i] = o;
}

// ---------------- kernel 1: per-token prep (exact f32 dots + compaction) ----------------
__global__ void prep_kernel(const float* __restrict__ hidden,
                            const int* __restrict__ target,   // int32 (JAX x64 disabled)
                            const float* __restrict__ weight,
                            const float* __restrict__ bias,
                            const float* __restrict__ cw,
                            const float* __restrict__ cb) {
    int gw = (int)((blockIdx.x * blockDim.x + threadIdx.x) >> 5);
    int lane = threadIdx.x & 31;
    if (gw >= NTOK) return;
    const int t = target[gw];
    const float4* h4  = reinterpret_cast<const float4*>(hidden + (size_t)gw * DIN);
    const float4* w4  = reinterpret_cast<const float4*>(weight + (size_t)t * DIN);
    const float4* c40 = reinterpret_cast<const float4*>(cw);
    const float4* c41 = reinterpret_cast<const float4*>(cw + DIN);
    const float4* c42 = reinterpret_cast<const float4*>(cw + 2 * DIN);
    float at = 0.f, a0 = 0.f, a1 = 0.f, a2 = 0.f;
#pragma unroll
    for (int j = 0; j < 8; j++) {
        int i = lane + 32 * j;
        float4 h = h4[i];
        float4 w = w4[i];
        at += h.x * w.x + h.y * w.y + h.z * w.z + h.w * w.w;
        float4 q = c40[i]; a0 += h.x * q.x + h.y * q.y + h.z * q.z + h.w * q.w;
        q = c41[i];        a1 += h.x * q.x + h.y * q.y + h.z * q.z + h.w * q.w;
        q = c42[i];        a2 += h.x * q.x + h.y * q.y + h.z * q.z + h.w * q.w;
    }
#pragma unroll
    for (int o = 16; o > 0; o >>= 1) {
        at += __shfl_xor_sync(0xffffffffu, at, o);
        a0 += __shfl_xor_sync(0xffffffffu, a0, o);
        a1 += __shfl_xor_sync(0xffffffffu, a1, o);
        a2 += __shfl_xor_sync(0xffffffffu, a2, o);
    }
    if (lane == 0) {
        g_tlogit[gw] = at + bias[t];
        g_clogit[gw][0] = a0 + cb[0];
        g_clogit[gw][1] = a1 + cb[1];
        g_clogit[gw][2] = a2 + cb[2];
        int r = (t < 20000) ? 0 : (t < 40000) ? 1 : (t < 200000) ? 2 : 3;
        g_cid[gw] = r;
        if (r > 0) {
            int idx = atomicAdd(&g_count[r], 1);
            g_list[r][idx] = gw;
        }
    }
}

// ---------------- kernel 2: merged bf16 HMMA GEMM + sum-of-exp epilogue ----------------
// bf16 sources. Per warp-LDG.128: 4 rows x 128B (full lines). 8 warps.
// A: warp owns 16 rows (4 LDG), B: warp owns 32 rows (8 LDG). Warp tile 64x64.
__global__ __launch_bounds__(GT, 1)
void gemm_sumexp(const float* __restrict__ bias) {
    extern __shared__ char smem[];
    const int tid = threadIdx.x;

    int nt = blockIdx.y;
    int region, lo, width;
    if (nt < NT0)                  { region = 0; lo = 0;      width = 20000;  }
    else if (nt < NT0 + NT1)       { region = 1; lo = 20000;  width = 20000;  nt -= NT0; }
    else if (nt < NT0 + NT1 + NT2) { region = 2; lo = 40000;  width = 160000; nt -= NT0 + NT1; }
    else                           { region = 3; lo = 200000; width = 67735;  nt -= NT0 + NT1 + NT2; }

    const int count = g_count[region];
    const int row0 = blockIdx.x * TM;        // M fastest -> weight-tile sharers concurrent
    if (row0 >= count) return;
    const int col0 = nt * TN;
    const uint32_t sb = smem_u32(smem);

    if (tid < TM) {
        int rr = row0 + tid;
        if (rr > count - 1) rr = count - 1;
        reinterpret_cast<int*>(smem + SLIST)[tid] = g_list[region][rr];
        reinterpret_cast<float*>(smem + SROW)[tid] = 0.0f;
    }
    {   // bias tile: 256 entries, one per thread
        int cls = col0 + tid;
        reinterpret_cast<float*>(smem + SBIAS)[tid] =
            (cls < width) ? bias[lo + cls] : __int_as_float(0xff800000);  // -inf
    }
    __syncthreads();

    const int* listp = reinterpret_cast<const int*>(smem + SLIST);
    const int lane = tid & 31, wid = tid >> 5;
    const int sub = lane >> 3;               // row within 4-row group
    const int pos = lane & 7;                // 16B unit within 128B row-chunk

    // chunk-invariant global element offsets (32-bit) + smem offsets
    uint32_t aoff[4], boff[8], soffA[4], soffB[8];
    bool bvalid[8];
#pragma unroll
    for (int j = 0; j < 4; j++) {
        int r = wid * 16 + j * 4 + sub;      // 0..127
        aoff[j] = (uint32_t)listp[r] * DIN + pos * 8;
        soffA[j] = SW((uint32_t)(r * 128 + pos * 16));
    }
#pragma unroll
    for (int j = 0; j < 8; j++) {
        int r = wid * 32 + j * 4 + sub;      // 0..255
        int cls = col0 + r;
        bvalid[j] = (cls < width);
        boff[j] = (uint32_t)(lo + (bvalid[j] ? cls : width - 1)) * DIN + pos * 8;
        soffB[j] = SW((uint32_t)(r * 128 + pos * 16));
    }

    const int wm = wid & 1, wn = wid >> 1;   // 2 M-warps x 4 N-warps

    float acc[4][8][4];
#pragma unroll
    for (int mi = 0; mi < 4; mi++)
#pragma unroll
        for (int nj = 0; nj < 8; nj++)
#pragma unroll
            for (int e = 0; e < 4; e++) acc[mi][nj][e] = 0.0f;

    uint4 ar[4], br[8];
#pragma unroll
    for (int j = 0; j < 4; j++)
        ar[j] = *reinterpret_cast<const uint4*>(g_hbf + aoff[j]);
#pragma unroll
    for (int j = 0; j < 8; j++)
        br[j] = *reinterpret_cast<const uint4*>(g_wbf + boff[j]);

#pragma unroll
    for (int j = 0; j < 4; j++) *reinterpret_cast<uint4*>(smem + SA(0) + soffA[j]) = ar[j];
#pragma unroll
    for (int j = 0; j < 8; j++) *reinterpret_cast<uint4*>(smem + SB(0) + soffB[j]) = br[j];
    __syncthreads();

    for (int kc = 0; kc < NKC; kc++) {
        const int cur = kc & 1;
        if (kc + 1 < NKC) {                    // prefetch next chunk
            const uint32_t kadd = (uint32_t)(kc + 1) * KC;
#pragma unroll
            for (int j = 0; j < 4; j++)
                ar[j] = *reinterpret_cast<const uint4*>(g_hbf + aoff[j] + kadd);
#pragma unroll
            for (int j = 0; j < 8; j++)
                br[j] = *reinterpret_cast<const uint4*>(g_wbf + boff[j] + kadd);
        }
#pragma unroll
        for (int ks = 0; ks < 4; ks++) {       // 4 x k16 per chunk
            uint32_t af[4][4];
#pragma unroll
            for (int mi = 0; mi < 4; mi++) {
                int r  = wm * 64 + mi * 16 + (lane & 15);
                int kb = ks * 16 + ((lane >> 4) << 3);
                lds_frag4(af[mi], sb + SA(cur) + SW((uint32_t)(r * 128 + kb * 2)));
            }
            uint32_t bf[4][4];
#pragma unroll
            for (int np = 0; np < 4; np++) {
                int cl = wn * 64 + np * 16 + (lane & 7) + ((lane & 16) ? 8 : 0);
                int kb = ks * 16 + ((lane & 8) ? 8 : 0);
                lds_frag4(bf[np], sb + SB(cur) + SW((uint32_t)(cl * 128 + kb * 2)));
            }
#pragma unroll
            for (int mi = 0; mi < 4; mi++)
#pragma unroll
                for (int nj = 0; nj < 8; nj++)
                    mma16816(acc[mi][nj], af[mi],
                             bf[nj >> 1][(nj & 1) * 2], bf[nj >> 1][(nj & 1) * 2 + 1]);
        }
        if (kc + 1 < NKC) {
            const int nxt = cur ^ 1;
#pragma unroll
            for (int j = 0; j < 4; j++) *reinterpret_cast<uint4*>(smem + SA(nxt) + soffA[j]) = ar[j];
#pragma unroll
            for (int j = 0; j < 8; j++) *reinterpret_cast<uint4*>(smem + SB(nxt) + soffB[j]) = br[j];
        }
        __syncthreads();
    }

    // ---- epilogue: exp(logit + bias), reduce to per-row sums ----
    const float* bs = reinterpret_cast<const float*>(smem + SBIAS);
    float* rowsum = reinterpret_cast<float*>(smem + SROW);
    float loc[8];
#pragma unroll
    for (int i = 0; i < 8; i++) loc[i] = 0.0f;
#pragma unroll
    for (int mi = 0; mi < 4; mi++) {
#pragma unroll
        for (int nj = 0; nj < 8; nj++) {
            int c = wn * 64 + nj * 8 + 2 * (lane & 3);
            float b0 = bs[c], b1 = bs[c + 1];
            loc[2*mi]   += __expf(acc[mi][nj][0] + b0) + __expf(acc[mi][nj][1] + b1);
            loc[2*mi+1] += __expf(acc[mi][nj][2] + b0) + __expf(acc[mi][nj][3] + b1);
        }
    }
#pragma unroll
    for (int i = 0; i < 8; i++) {
        loc[i] += __shfl_xor_sync(0xffffffffu, loc[i], 1);
        loc[i] += __shfl_xor_sync(0xffffffffu, loc[i], 2);
    }
    if ((lane & 3) == 0) {
        int g = lane >> 2;
#pragma unroll
        for (int mi = 0; mi < 4; mi++) {
            atomicAdd(&rowsum[wm * 64 + mi * 16 + g],     loc[2*mi]);
            atomicAdd(&rowsum[wm * 64 + mi * 16 + g + 8], loc[2*mi+1]);
        }
    }
    __syncthreads();
    if (tid < TM && row0 + tid < count)
        atomicAdd(&g_S[region][listp[tid]], rowsum[tid]);
}

// ---------------- kernel 3: finalize NLL ----------------
__global__ void finalize_kernel(float* __restrict__ out) {
    int t = blockIdx.x * blockDim.x + threadIdx.x;
    if (t >= NTOK) return;
    int r = g_cid[t];
    float ch = __expf(g_clogit[t][0]) + __expf(g_clogit[t][1]) + __expf(g_clogit[t][2]);
    float lse_head = __logf(g_S[0][t] + ch);
    float nll;
    if (r == 0) {
        nll = lse_head - g_tlogit[t];
    } else {
        float lse_tail = __logf(g_S[r][t]);
        // reference: head_logprob[:, -i] for region i -> cluster column (3 - i)
        nll = lse_head + lse_tail - g_clogit[t][3 - r] - g_tlogit[t];
    }
    out[t] = nll;
}

// ---------------- launcher ----------------
extern "C" void kernel_launch(void* const* d_in, const int* in_sizes, int n_in,
                              void* d_out, int out_size) {
    const float* hidden = (const float*)d_in[0];
    const int*   target = (const int*)d_in[1];
    const float* weight = (const float*)d_in[2];
    const float* bias   = (const float*)d_in[3];
    const float* cw     = (const float*)d_in[4];
    const float* cb     = (const float*)d_in[5];
    float* out = (float*)d_out;

    cudaFuncSetAttribute(gemm_sumexp,
                         cudaFuncAttributeMaxDynamicSharedMemorySize, SMEM_TOTAL);

    zero_kernel<<<1, 256>>>();
    prep_kernel<<<128, 256>>>(hidden, target, weight, bias, cw, cb);

    // bf16 pre-conversion into static buffers (pure function of inputs)
    __nv_bfloat16* d_wbf = nullptr; cudaGetSymbolAddress((void**)&d_wbf, g_wbf);
    __nv_bfloat16* d_hbf = nullptr; cudaGetSymbolAddress((void**)&d_hbf, g_hbf);
    const size_t w8 = WELEMS / 8;                       // 34,270,080
    convert_kernel<<<(unsigned)((w8 + 255) / 256), 256>>>(weight, d_wbf, w8);
    const size_t h8 = (size_t)NTOK * DIN / 8;           // 131,072
    convert_kernel<<<(unsigned)((h8 + 255) / 256), 256>>>(hidden, d_hbf, h8);

    // one merged launch over all regions; M-tiles fastest
    gemm_sumexp<<<dim3(8, NT_TOTAL), GT, SMEM_TOTAL>>>(bias);

    finalize_kernel<<<4, 256>>>(out);
}

// round 8
// speedup vs baseline: 3.0028x; 1.0499x over previous
#include <cuda_runtime.h>
#include <cuda_bf16.h>
#include <cstdint>

// ---------------- problem constants ----------------
#define NTOK 1024
#define DIN  1024
#define NCLS 267735
#define WELEMS ((size_t)NCLS * DIN)          // 274,160,640
// regions: [0,20000) head, [20000,40000), [40000,200000), [200000,267735)

// ---------------- GEMM tile config ----------------
#define TM 128
#define TN 256
#define KC 64
#define NKC 16              // DIN / KC
#define GT 256              // 8 warps: 2 M-warps x 4 N-warps, warp tile 64x64

// N-tile counts per region (classes / TN, ceil)
#define NT0 79
#define NT1 79
#define NT2 625
#define NT3 265
#define NT_TOTAL (NT0 + NT1 + NT2 + NT3)   // 1048

// smem byte offsets. A: 2 x 16KB, B: 2 x 32KB (bf16, 128B rows, SW128)
#define SA(buf) ((buf) * 16384)
#define SB(buf) (32768 + (buf) * 32768)
#define SBIAS 98304                          // 256 f32
#define SLIST 99328                          // 128 int
#define SROW  99840                          // 128 f32
#define SMEM_TOTAL 100352

#define SW(o) ((o) ^ (((o) >> 3) & 0x70))    // SW128 swizzle on byte offsets

// ---------------- device scratch (static; no allocation) ----------------
__device__ __nv_bfloat16 g_wbf[WELEMS];      // bf16 weight (548 MB)
__device__ __nv_bfloat16 g_hbf[NTOK * DIN];  // bf16 hidden
__device__ float g_S[4][NTOK];
__device__ int   g_list[4][NTOK];
__device__ int   g_count[4];
__device__ float g_tlogit[NTOK];
__device__ float g_clogit[NTOK][3];
__device__ int   g_cid[NTOK];

// ---------------- small helpers ----------------
__device__ __forceinline__ uint32_t smem_u32(const void* p) {
    uint32_t a;
    asm("{ .reg .u64 t; cvta.to.shared.u64 t, %1; cvt.u32.u64 %0, t; }" : "=r"(a) : "l"(p));
    return a;
}
__device__ __forceinline__ uint32_t pack_bf16(float a, float b) {
    __nv_bfloat162 h = __floats2bfloat162_rn(a, b);
    return *reinterpret_cast<uint32_t*>(&h);
}
__device__ __forceinline__ void cp_async16(uint32_t saddr, const void* gaddr) {
    asm volatile("cp.async.cg.shared.global [%0], [%1], 16;" :: "r"(saddr), "l"(gaddr));
}
#define CP_COMMIT() asm volatile("cp.async.commit_group;" ::: "memory")
#define CP_WAIT(n)  asm volatile("cp.async.wait_group %0;" :: "n"(n) : "memory")
__device__ __forceinline__ void lds_frag4(uint32_t r[4], uint32_t addr) {
    asm volatile("ldmatrix.sync.aligned.m8n8.x4.shared.b16 {%0,%1,%2,%3}, [%4];"
        : "=r"(r[0]), "=r"(r[1]), "=r"(r[2]), "=r"(r[3]) : "r"(addr));
}
__device__ __forceinline__ void mma16816(float d[4], const uint32_t a[4],
                                         uint32_t b0, uint32_t b1) {
    asm volatile("mma.sync.aligned.m16n8k16.row.col.f32.bf16.bf16.f32 "
        "{%0,%1,%2,%3}, {%4,%5,%6,%7}, {%8,%9}, {%0,%1,%2,%3};"
        : "+f"(d[0]), "+f"(d[1]), "+f"(d[2]), "+f"(d[3])
        : "r"(a[0]), "r"(a[1]), "r"(a[2]), "r"(a[3]), "r"(b0), "r"(b1));
}

// ---------------- kernel 0: reset scratch ----------------
__global__ void zero_kernel() {
    int t = threadIdx.x;
    for (int i = t; i < 4 * NTOK; i += blockDim.x) (&g_S[0][0])[i] = 0.0f;
    for (int i = t; i < NTOK; i += blockDim.x) g_list[0][i] = i;
    if (t == 0) g_count[0] = NTOK;
    if (t >= 1 && t < 4) g_count[t] = 0;
}

// ---------------- f32 -> bf16 streaming convert (8 elems / thread) ----------------
__global__ void convert_kernel(const float* __restrict__ src,
                               __nv_bfloat16* __restrict__ dst, size_t n8) {
    size_t i = (size_t)blockIdx.x * blockDim.x + threadIdx.x;
    if (i >= n8) return;
    const float4* p = reinterpret_cast<const float4*>(src) + i * 2;
    float4 a = p[0], b = p[1];
    uint4 o;
    o.x = pack_bf16(a.x, a.y); o.y = pack_bf16(a.z, a.w);
    o.z = pack_bf16(b.x, b.y); o.w = pack_bf16(b.z, b.w);
    reinterpret_cast<uint4*>(dst)[i] = o;
}

// ---------------- kernel 1: per-token prep (exact f32 dots + compaction) ----------------
__global__ void prep_kernel(const float* __restrict__ hidden,
                            const int* __restrict__ target,   // int32 (JAX x64 disabled)
                            const float* __restrict__ weight,
                            const float* __restrict__ bias,
                            const float* __restrict__ cw,
                            const float* __restrict__ cb) {
    int gw = (int)((blockIdx.x * blockDim.x + threadIdx.x) >> 5);
    int lane = threadIdx.x & 31;
    if (gw >= NTOK) return;
    const int t = target[gw];
    const float4* h4  = reinterpret_cast<const float4*>(hidden + (size_t)gw * DIN);
    const float4* w4  = reinterpret_cast<const float4*>(weight + (size_t)t * DIN);
    const float4* c40 = reinterpret_cast<const float4*>(cw);
    const float4* c41 = reinterpret_cast<const float4*>(cw + DIN);
    const float4* c42 = reinterpret_cast<const float4*>(cw + 2 * DIN);
    float at = 0.f, a0 = 0.f, a1 = 0.f, a2 = 0.f;
#pragma unroll
    for (int j = 0; j < 8; j++) {
        int i = lane + 32 * j;
        float4 h = h4[i];
        float4 w = w4[i];
        at += h.x * w.x + h.y * w.y + h.z * w.z + h.w * w.w;
        float4 q = c40[i]; a0 += h.x * q.x + h.y * q.y + h.z * q.z + h.w * q.w;
        q = c41[i];        a1 += h.x * q.x + h.y * q.y + h.z * q.z + h.w * q.w;
        q = c42[i];        a2 += h.x * q.x + h.y * q.y + h.z * q.z + h.w * q.w;
    }
#pragma unroll
    for (int o = 16; o > 0; o >>= 1) {
        at += __shfl_xor_sync(0xffffffffu, at, o);
        a0 += __shfl_xor_sync(0xffffffffu, a0, o);
        a1 += __shfl_xor_sync(0xffffffffu, a1, o);
        a2 += __shfl_xor_sync(0xffffffffu, a2, o);
    }
    if (lane == 0) {
        g_tlogit[gw] = at + bias[t];
        g_clogit[gw][0] = a0 + cb[0];
        g_clogit[gw][1] = a1 + cb[1];
        g_clogit[gw][2] = a2 + cb[2];
        int r = (t < 20000) ? 0 : (t < 40000) ? 1 : (t < 200000) ? 2 : 3;
        g_cid[gw] = r;
        if (r > 0) {
            int idx = atomicAdd(&g_count[r], 1);
            g_list[r][idx] = gw;
        }
    }
}

// ---------------- kernel 2: merged bf16 HMMA GEMM (cp.async pipeline) ----------------
// bf16 sources. Per warp-cp.async wave: 4 rows x 128B (full lines).
// A: warp owns 16 rows (4 ops/thread), B: warp owns 32 rows (8 ops/thread).
__global__ __launch_bounds__(GT, 1)
void gemm_sumexp(const float* __restrict__ bias) {
    extern __shared__ char smem[];
    const int tid = threadIdx.x;

    int nt = blockIdx.y;
    int region, lo, width;
    if (nt < NT0)                  { region = 0; lo = 0;      width = 20000;  }
    else if (nt < NT0 + NT1)       { region = 1; lo = 20000;  width = 20000;  nt -= NT0; }
    else if (nt < NT0 + NT1 + NT2) { region = 2; lo = 40000;  width = 160000; nt -= NT0 + NT1; }
    else                           { region = 3; lo = 200000; width = 67735;  nt -= NT0 + NT1 + NT2; }

    const int count = g_count[region];
    const int row0 = blockIdx.x * TM;        // M fastest -> weight-tile sharers concurrent
    if (row0 >= count) return;
    const int col0 = nt * TN;
    const uint32_t sb = smem_u32(smem);

    if (tid < TM) {
        int rr = row0 + tid;
        if (rr > count - 1) rr = count - 1;
        reinterpret_cast<int*>(smem + SLIST)[tid] = g_list[region][rr];
        reinterpret_cast<float*>(smem + SROW)[tid] = 0.0f;
    }
    {   // bias tile: 256 entries, one per thread
        int cls = col0 + tid;
        reinterpret_cast<float*>(smem + SBIAS)[tid] =
            (cls < width) ? bias[lo + cls] : __int_as_float(0xff800000);  // -inf
    }
    __syncthreads();

    const int* listp = reinterpret_cast<const int*>(smem + SLIST);
    const int lane = tid & 31, wid = tid >> 5;
    const int sub = lane >> 3;               // row within 4-row group
    const int pos = lane & 7;                // 16B unit within 128B row-chunk

    // chunk-invariant global element offsets (32-bit) + smem offsets
    uint32_t aoff[4], boff[8], soffA[4], soffB[8];
#pragma unroll
    for (int j = 0; j < 4; j++) {
        int r = wid * 16 + j * 4 + sub;      // 0..127
        aoff[j] = (uint32_t)listp[r] * DIN + pos * 8;
        soffA[j] = SW((uint32_t)(r * 128 + pos * 16));
    }
#pragma unroll
    for (int j = 0; j < 8; j++) {
        int r = wid * 32 + j * 4 + sub;      // 0..255
        int cls = col0 + r;
        // OOB rows clamp to a valid row; their bias is -inf so exp() kills them
        boff[j] = (uint32_t)(lo + ((cls < width) ? cls : width - 1)) * DIN + pos * 8;
        soffB[j] = SW((uint32_t)(r * 128 + pos * 16));
    }

    const int wm = wid & 1, wn = wid >> 1;   // 2 M-warps x 4 N-warps

    float acc[4][8][4];
#pragma unroll
    for (int mi = 0; mi < 4; mi++)
#pragma unroll
        for (int nj = 0; nj < 8; nj++)
#pragma unroll
            for (int e = 0; e < 4; e++) acc[mi][nj][e] = 0.0f;

    // ---- async load of chunk 0 ----
#pragma unroll
    for (int j = 0; j < 4; j++)
        cp_async16(sb + SA(0) + soffA[j], g_hbf + aoff[j]);
#pragma unroll
    for (int j = 0; j < 8; j++)
        cp_async16(sb + SB(0) + soffB[j], g_wbf + boff[j]);
    CP_COMMIT();

    for (int kc = 0; kc < NKC; kc++) {
        const int cur = kc & 1;
        if (kc + 1 < NKC) {                    // async-load next chunk into other buffer
            const int nxt = cur ^ 1;
            const uint32_t kadd = (uint32_t)(kc + 1) * KC;
#pragma unroll
            for (int j = 0; j < 4; j++)
                cp_async16(sb + SA(nxt) + soffA[j], g_hbf + aoff[j] + kadd);
#pragma unroll
            for (int j = 0; j < 8; j++)
                cp_async16(sb + SB(nxt) + soffB[j], g_wbf + boff[j] + kadd);
            CP_COMMIT();
            CP_WAIT(1);                        // chunk kc arrived; kc+1 in flight
        } else {
            CP_WAIT(0);
        }
        __syncthreads();
#pragma unroll
        for (int ks = 0; ks < 4; ks++) {       // 4 x k16 per chunk
            uint32_t af[4][4];
#pragma unroll
            for (int mi = 0; mi < 4; mi++) {
                int r  = wm * 64 + mi * 16 + (lane & 15);
                int kb = ks * 16 + ((lane >> 4) << 3);
                lds_frag4(af[mi], sb + SA(cur) + SW((uint32_t)(r * 128 + kb * 2)));
            }
            uint32_t bf[4][4];
#pragma unroll
            for (int np = 0; np < 4; np++) {
                int cl = wn * 64 + np * 16 + (lane & 7) + ((lane & 16) ? 8 : 0);
                int kb = ks * 16 + ((lane & 8) ? 8 : 0);
                lds_frag4(bf[np], sb + SB(cur) + SW((uint32_t)(cl * 128 + kb * 2)));
            }
#pragma unroll
            for (int mi = 0; mi < 4; mi++)
#pragma unroll
                for (int nj = 0; nj < 8; nj++)
                    mma16816(acc[mi][nj], af[mi],
                             bf[nj >> 1][(nj & 1) * 2], bf[nj >> 1][(nj & 1) * 2 + 1]);
        }
        __syncthreads();                       // compute done before next wait/overwrite
    }

    // ---- epilogue: exp(logit + bias), reduce to per-row sums ----
    const float* bs = reinterpret_cast<const float*>(smem + SBIAS);
    float* rowsum = reinterpret_cast<float*>(smem + SROW);
    float loc[8];
#pragma unroll
    for (int i = 0; i < 8; i++) loc[i] = 0.0f;
#pragma unroll
    for (int mi = 0; mi < 4; mi++) {
#pragma unroll
        for (int nj = 0; nj < 8; nj++) {
            int c = wn * 64 + nj * 8 + 2 * (lane & 3);
            float b0 = bs[c], b1 = bs[c + 1];
            loc[2*mi]   += __expf(acc[mi][nj][0] + b0) + __expf(acc[mi][nj][1] + b1);
            loc[2*mi+1] += __expf(acc[mi][nj][2] + b0) + __expf(acc[mi][nj][3] + b1);
        }
    }
#pragma unroll
    for (int i = 0; i < 8; i++) {
        loc[i] += __shfl_xor_sync(0xffffffffu, loc[i], 1);
        loc[i] += __shfl_xor_sync(0xffffffffu, loc[i], 2);
    }
    if ((lane & 3) == 0) {
        int g = lane >> 2;
#pragma unroll
        for (int mi = 0; mi < 4; mi++) {
            atomicAdd(&rowsum[wm * 64 + mi * 16 + g],     loc[2*mi]);
            atomicAdd(&rowsum[wm * 64 + mi * 16 + g + 8], loc[2*mi+1]);
        }
    }
    __syncthreads();
    if (tid < TM && row0 + tid < count)
        atomicAdd(&g_S[region][listp[tid]], rowsum[tid]);
}

// ---------------- kernel 3: finalize NLL ----------------
__global__ void finalize_kernel(float* __restrict__ out) {
    int t = blockIdx.x * blockDim.x + threadIdx.x;
    if (t >= NTOK) return;
    int r = g_cid[t];
    float ch = __expf(g_clogit[t][0]) + __expf(g_clogit[t][1]) + __expf(g_clogit[t][2]);
    float lse_head = __logf(g_S[0][t] + ch);
    float nll;
    if (r == 0) {
        nll = lse_head - g_tlogit[t];
    } else {
        float lse_tail = __logf(g_S[r][t]);
        // reference: head_logprob[:, -i] for region i -> cluster column (3 - i)
        nll = lse_head + lse_tail - g_clogit[t][3 - r] - g_tlogit[t];
    }
    out[t] = nll;
}

// ---------------- launcher ----------------
extern "C" void kernel_launch(void* const* d_in, const int* in_sizes, int n_in,
                              void* d_out, int out_size) {
    const float* hidden = (const float*)d_in[0];
    const int*   target = (const int*)d_in[1];
    const float* weight = (const float*)d_in[2];
    const float* bias   = (const float*)d_in[3];
    const float* cw     = (const float*)d_in[4];
    const float* cb     = (const float*)d_in[5];
    float* out = (float*)d_out;

    cudaFuncSetAttribute(gemm_sumexp,
                         cudaFuncAttributeMaxDynamicSharedMemorySize, SMEM_TOTAL);

    zero_kernel<<<1, 256>>>();
    prep_kernel<<<128, 256>>>(hidden, target, weight, bias, cw, cb);

    // bf16 pre-conversion into static buffers (pure function of inputs)
    __nv_bfloat16* d_wbf = nullptr; cudaGetSymbolAddress((void**)&d_wbf, g_wbf);
    __nv_bfloat16* d_hbf = nullptr; cudaGetSymbolAddress((void**)&d_hbf, g_hbf);
    const size_t w8 = WELEMS / 8;                       // 34,270,080
    convert_kernel<<<(unsigned)((w8 + 255) / 256), 256>>>(weight, d_wbf, w8);
    const size_t h8 = (size_t)NTOK * DIN / 8;           // 131,072
    convert_kernel<<<(unsigned)((h8 + 255) / 256), 256>>>(hidden, d_hbf, h8);

    // one merged launch over all regions; M-tiles fastest
    gemm_sumexp<<<dim3(8, NT_TOTAL), GT, SMEM_TOTAL>>>(bias);

    finalize_kernel<<<4, 256>>>(out);
}